// round 3
// baseline (speedup 1.0000x reference)
#include <cuda_runtime.h>
#include <math.h>

// Problem constants
#define NPTS   12288      // 96*128 points
#define KDIM   512        // channels
#define NTILES 96         // 12288 / 128
#define BM     128
#define BN     128
#define BK     16
#define TILE_LD 129       // padded leading dim for smem tile (conflict-free scans)

// packed fp32x2 FMA (sm_100+): d.lo += a.lo*b.lo ; d.hi += a.hi*b.hi (fused, rn)
#define FMA_F32X2(d, a, b) \
    asm("fma.rn.f32x2 %0, %1, %2, %0;" : "+l"(d) : "l"(a), "l"(b))

// ---------------- scratch (device globals: allocation-guard safe) ------------
__device__ float g_invA[NPTS];
__device__ float g_invB[NPTS];
__device__ float g_rowPV[NPTS * NTILES * 2];
__device__ int   g_rowPI[NPTS * NTILES * 2];
__device__ float g_colPV[NPTS * NTILES * 2];
__device__ int   g_colPI[NPTS * NTILES * 2];
__device__ int   g_nn12[NPTS];
__device__ float g_s12_0[NPTS];
__device__ float g_s12_1[NPTS];
__device__ int   g_nn21[NPTS];
__device__ float g_r21[NPTS];

// ---------------- kernel 1: inverse L2 norms ---------------------------------
__global__ void invnorm_kernel(const float* __restrict__ A, const float* __restrict__ B) {
    int p = blockIdx.x * blockDim.x + threadIdx.x;
    if (p >= NPTS) return;
    float sa = 0.f, sb = 0.f;
#pragma unroll 8
    for (int c = 0; c < KDIM; c++) {
        float a = A[c * NPTS + p];
        float b = B[c * NPTS + p];
        sa = fmaf(a, a, sa);
        sb = fmaf(b, b, sb);
    }
    g_invA[p] = 1.0f / sqrtf(sa);
    g_invB[p] = 1.0f / sqrtf(sb);
}

// ---------------- kernel 2: fused GEMM (FFMA2) + per-tile top-2 --------------
// A tile is stored DUPLICATED in smem (x,x,y,y,...) so packed 64-bit operand
// pairs for fma.rn.f32x2 load directly with no broadcast MOVs.
__global__ void __launch_bounds__(256, 2)
gemm_top2_kernel(const float* __restrict__ A, const float* __restrict__ B) {
    extern __shared__ float smem[];
    float* As2  = smem;                  // [BK][2*BM] duplicated: 4096 floats
    float* Bs   = smem + BK * 2 * BM;    // [BK][BN]:               2048 floats
    float* tile = smem;                  // [BM][TILE_LD] after K loop (aliases)

    const int tid = threadIdx.x;
    const int tx  = tid & 15;            // 0..15 -> col micro-tile
    const int ty  = tid >> 4;            // 0..15 -> row micro-tile
    const int bj  = blockIdx.x;
    const int bi  = blockIdx.y;
    const int bm0 = bi * BM;
    const int bn0 = bj * BN;

    // cooperative-load coordinates (2 vectors per thread per operand)
    const int t0  = tid;
    const int t1  = tid + 256;
    const int kk0 = t0 >> 5, mm0 = (t0 & 31) << 2;
    const int kk1 = t1 >> 5, mm1 = (t1 & 31) << 2;

    unsigned long long acc2[8][4];
#pragma unroll
    for (int i = 0; i < 8; i++)
#pragma unroll
        for (int j = 0; j < 4; j++) acc2[i][j] = 0ULL;  // packed (0.f, 0.f)

    // prefetch slab 0 into registers
    float4 pa0 = *(const float4*)&A[kk0 * NPTS + bm0 + mm0];
    float4 pa1 = *(const float4*)&A[kk1 * NPTS + bm0 + mm1];
    float4 pb0 = *(const float4*)&B[kk0 * NPTS + bn0 + mm0];
    float4 pb1 = *(const float4*)&B[kk1 * NPTS + bn0 + mm1];

    for (int k0 = 0; k0 < KDIM; k0 += BK) {
        // commit prefetched slab to smem (A duplicated)
        float4 lo0 = make_float4(pa0.x, pa0.x, pa0.y, pa0.y);
        float4 hi0 = make_float4(pa0.z, pa0.z, pa0.w, pa0.w);
        float4 lo1 = make_float4(pa1.x, pa1.x, pa1.y, pa1.y);
        float4 hi1 = make_float4(pa1.z, pa1.z, pa1.w, pa1.w);
        *(float4*)&As2[kk0 * (2 * BM) + 2 * mm0]     = lo0;
        *(float4*)&As2[kk0 * (2 * BM) + 2 * mm0 + 4] = hi0;
        *(float4*)&As2[kk1 * (2 * BM) + 2 * mm1]     = lo1;
        *(float4*)&As2[kk1 * (2 * BM) + 2 * mm1 + 4] = hi1;
        *(float4*)&Bs[kk0 * BN + mm0] = pb0;
        *(float4*)&Bs[kk1 * BN + mm1] = pb1;
        __syncthreads();

        // prefetch next slab while computing this one
        if (k0 + BK < KDIM) {
            int g0 = (k0 + BK + kk0) * NPTS;
            int g1 = (k0 + BK + kk1) * NPTS;
            pa0 = *(const float4*)&A[g0 + bm0 + mm0];
            pa1 = *(const float4*)&A[g1 + bm0 + mm1];
            pb0 = *(const float4*)&B[g0 + bn0 + mm0];
            pb1 = *(const float4*)&B[g1 + bn0 + mm1];
        }

#pragma unroll
        for (int kk = 0; kk < BK; kk++) {
            // a pairs: 8 duplicated values = 16 floats = 4x 128-bit loads
            ulonglong2 a01 = *(const ulonglong2*)&As2[kk * (2 * BM) + ty * 16 + 0];
            ulonglong2 a23 = *(const ulonglong2*)&As2[kk * (2 * BM) + ty * 16 + 4];
            ulonglong2 a45 = *(const ulonglong2*)&As2[kk * (2 * BM) + ty * 16 + 8];
            ulonglong2 a67 = *(const ulonglong2*)&As2[kk * (2 * BM) + ty * 16 + 12];
            // b pairs: 8 distinct values = 4 packed pairs = 2x 128-bit loads
            ulonglong2 b01 = *(const ulonglong2*)&Bs[kk * BN + tx * 8];
            ulonglong2 b23 = *(const ulonglong2*)&Bs[kk * BN + tx * 8 + 4];
            unsigned long long ap[8] = { a01.x, a01.y, a23.x, a23.y,
                                         a45.x, a45.y, a67.x, a67.y };
            unsigned long long bp[4] = { b01.x, b01.y, b23.x, b23.y };
#pragma unroll
            for (int i = 0; i < 8; i++) {
#pragma unroll
                for (int j = 0; j < 4; j++)
                    FMA_F32X2(acc2[i][j], ap[i], bp[j]);
            }
        }
        __syncthreads();
    }

    // epilogue: unpack, scale by inverse norms, stage full tile in smem
    float ia[8], ib[8];
#pragma unroll
    for (int i = 0; i < 8; i++) {
        ia[i] = g_invA[bm0 + ty * 8 + i];
        ib[i] = g_invB[bn0 + tx * 8 + i];
    }
#pragma unroll
    for (int i = 0; i < 8; i++) {
#pragma unroll
        for (int j = 0; j < 4; j++) {
            float vlo, vhi;
            asm("mov.b64 {%0, %1}, %2;" : "=f"(vlo), "=f"(vhi) : "l"(acc2[i][j]));
            tile[(ty * 8 + i) * TILE_LD + tx * 8 + 2 * j]     = vlo * ia[i] * ib[2 * j];
            tile[(ty * 8 + i) * TILE_LD + tx * 8 + 2 * j + 1] = vhi * ia[i] * ib[2 * j + 1];
        }
    }
    __syncthreads();

    // top-2 scans: threads 0..127 rows, 128..255 columns
    if (tid < 128) {
        int r = tid;
        float v0 = -2.f, v1 = -2.f;
        int   i0 = 0,    i1 = 0;
#pragma unroll 4
        for (int j = 0; j < BN; j++) {
            float v = tile[r * TILE_LD + j];
            if (v > v0) { v1 = v0; i1 = i0; v0 = v; i0 = bn0 + j; }
            else if (v > v1) { v1 = v; i1 = bn0 + j; }
        }
        int base = ((bm0 + r) * NTILES + bj) * 2;
        g_rowPV[base] = v0; g_rowPV[base + 1] = v1;
        g_rowPI[base] = i0; g_rowPI[base + 1] = i1;
    } else {
        int c = tid - 128;
        float v0 = -2.f, v1 = -2.f;
        int   i0 = 0,    i1 = 0;
#pragma unroll 4
        for (int r = 0; r < BM; r++) {
            float v = tile[r * TILE_LD + c];
            if (v > v0) { v1 = v0; i1 = i0; v0 = v; i0 = bm0 + r; }
            else if (v > v1) { v1 = v; i1 = bm0 + r; }
        }
        int base = ((bn0 + c) * NTILES + bi) * 2;
        g_colPV[base] = v0; g_colPV[base + 1] = v1;
        g_colPI[base] = i0; g_colPI[base + 1] = i1;
    }
}

// ---------------- kernel 3: merge partials -----------------------------------
__global__ void merge_kernel() {
    int t = blockIdx.x * blockDim.x + threadIdx.x;
    if (t < NPTS) {
        int r = t;
        float v0 = -2.f, v1 = -2.f;
        int   i0 = 0,    i1 = 0;
        for (int tt = 0; tt < NTILES; tt++) {
            int base = (r * NTILES + tt) * 2;
            float a0 = g_rowPV[base];     int j0 = g_rowPI[base];
            float a1 = g_rowPV[base + 1]; int j1 = g_rowPI[base + 1];
            if (a0 > v0) { v1 = v0; i1 = i0; v0 = a0; i0 = j0; }
            else if (a0 > v1) { v1 = a0; i1 = j0; }
            if (a1 > v0) { v1 = v0; i1 = i0; v0 = a1; i0 = j1; }
            else if (a1 > v1) { v1 = a1; i1 = j1; }
        }
        g_nn12[r] = i0; g_s12_0[r] = v0; g_s12_1[r] = v1;
    } else if (t < 2 * NPTS) {
        int c = t - NPTS;
        float v0 = -2.f, v1 = -2.f;
        int   i0 = 0,    i1 = 0;
        for (int tt = 0; tt < NTILES; tt++) {
            int base = (c * NTILES + tt) * 2;
            float a0 = g_colPV[base];     int j0 = g_colPI[base];
            float a1 = g_colPV[base + 1]; int j1 = g_colPI[base + 1];
            if (a0 > v0) { v1 = v0; i1 = i0; v0 = a0; i0 = j0; }
            else if (a0 > v1) { v1 = a0; i1 = j0; }
            if (a1 > v0) { v1 = v0; i1 = i0; v0 = a1; i0 = j1; }
            else if (a1 > v1) { v1 = a1; i1 = j1; }
        }
        float d0 = 2.f - 2.f * v0;
        float d1 = 2.f - 2.f * v1;
        g_nn21[c] = i0;
        g_r21[c]  = d0 / (d1 + 1e-8f);
    }
}

// ---------------- kernel 4: mutual NN + ratio mask, write outputs ------------
__global__ void final_kernel(float* __restrict__ out) {
    int r = blockIdx.x * blockDim.x + threadIdx.x;
    if (r >= NPTS) return;
    int   j  = g_nn12[r];
    float s0 = g_s12_0[r];
    float s1 = g_s12_1[r];
    float ratio12 = (2.f - 2.f * s0) / ((2.f - 2.f * s1) + 1e-8f);
    bool m = (g_nn21[j] == r) && (ratio12 <= 0.95f) && (g_r21[j] <= 0.95f);
    out[r]             = m ? s0 : 0.f;      // masked_sim
    out[NPTS + r]      = (float)j;          // nn12
    out[2 * NPTS + r]  = m ? 1.f : 0.f;     // mask
}

// ---------------- launcher ----------------------------------------------------
extern "C" void kernel_launch(void* const* d_in, const int* in_sizes, int n_in,
                              void* d_out, int out_size) {
    const float* A = (const float*)d_in[0];
    const float* B = (const float*)d_in[1];
    float* out = (float*)d_out;

    const int smem_bytes = BM * TILE_LD * sizeof(float);  // 66048 B (>= GEMM smem 24KB)
    cudaFuncSetAttribute(gemm_top2_kernel,
                         cudaFuncAttributeMaxDynamicSharedMemorySize, smem_bytes);

    invnorm_kernel<<<(NPTS + 255) / 256, 256>>>(A, B);

    dim3 grid(NTILES, NTILES);
    gemm_top2_kernel<<<grid, 256, smem_bytes>>>(A, B);

    merge_kernel<<<(2 * NPTS + 255) / 256, 256>>>();

    final_kernel<<<(NPTS + 255) / 256, 256>>>(out);
}

// round 6
// speedup vs baseline: 1.2415x; 1.2415x over previous
#include <cuda_runtime.h>
#include <math.h>

// Problem constants
#define NPTS   12288      // 96*128 points
#define KDIM   512        // channels
#define NTILES 96         // 12288 / 128
#define BM     128
#define BN     128
#define BK     16
#define NSLABS (KDIM / BK)   // 32
#define TILE_LD 129          // padded leading dim for smem tile scans
#define BUF_FLOATS 4096      // one stage: As(16*128) + Bs(16*128)

// ---------------- scratch (device globals: allocation-guard safe) ------------
__device__ float g_invA[NPTS];
__device__ float g_invB[NPTS];
__device__ float g_rowPV[NPTS * NTILES * 2];
__device__ int   g_rowPI[NPTS * NTILES * 2];
__device__ float g_colPV[NPTS * NTILES * 2];
__device__ int   g_colPI[NPTS * NTILES * 2];
__device__ int   g_nn12[NPTS];
__device__ float g_s12_0[NPTS];
__device__ float g_s12_1[NPTS];
__device__ int   g_nn21[NPTS];
__device__ float g_r21[NPTS];

// ---------------- kernel 1: inverse L2 norms ---------------------------------
__global__ void invnorm_kernel(const float* __restrict__ A, const float* __restrict__ B) {
    int p = blockIdx.x * blockDim.x + threadIdx.x;
    if (p >= NPTS) return;
    float sa = 0.f, sb = 0.f;
#pragma unroll 8
    for (int c = 0; c < KDIM; c++) {
        float a = A[c * NPTS + p];
        float b = B[c * NPTS + p];
        sa = fmaf(a, a, sa);
        sb = fmaf(b, b, sb);
    }
    g_invA[p] = 1.0f / sqrtf(sa);
    g_invB[p] = 1.0f / sqrtf(sb);
}

// ---------------- kernel 2: double-buffered GEMM + per-tile top-2 ------------
// C[bm0+r, bn0+c] = (sum_k A[k,bm0+r]*B[k,bn0+c]) * invA * invB
// A, B layout: [KDIM][NPTS] channel-major -> point dim contiguous.
__global__ void __launch_bounds__(256, 2)
gemm_top2_kernel(const float* __restrict__ A, const float* __restrict__ B) {
    extern __shared__ float smem[];
    float* tile = smem;                 // [BM][TILE_LD] after K loop (aliases bufs)

    const int tid = threadIdx.x;
    const int tx  = tid & 15;           // 0..15 -> col micro-tile
    const int ty  = tid >> 4;           // 0..15 -> row micro-tile
    const int bj  = blockIdx.x;
    const int bi  = blockIdx.y;
    const int bm0 = bi * BM;
    const int bn0 = bj * BN;

    // cooperative-load coordinates: 512 float4 per operand per slab, 2/thread
    const int kk0 = tid >> 5,           mm0 = (tid & 31) << 2;
    const int kk1 = (tid + 256) >> 5,   mm1 = ((tid + 256) & 31) << 2;

    float acc[8][8];
#pragma unroll
    for (int i = 0; i < 8; i++)
#pragma unroll
        for (int j = 0; j < 8; j++) acc[i][j] = 0.f;

    // prologue: load slab 0, stage into buffer 0
    float4 pa0 = *(const float4*)&A[kk0 * NPTS + bm0 + mm0];
    float4 pa1 = *(const float4*)&A[kk1 * NPTS + bm0 + mm1];
    float4 pb0 = *(const float4*)&B[kk0 * NPTS + bn0 + mm0];
    float4 pb1 = *(const float4*)&B[kk1 * NPTS + bn0 + mm1];
    *(float4*)&smem[kk0 * BM + mm0]        = pa0;
    *(float4*)&smem[kk1 * BM + mm1]        = pa1;
    *(float4*)&smem[2048 + kk0 * BN + mm0] = pb0;
    *(float4*)&smem[2048 + kk1 * BN + mm1] = pb1;
    __syncthreads();

    for (int s = 0; s < NSLABS; s++) {
        const float* As = smem + (s & 1) * BUF_FLOATS;
        const float* Bs = As + 2048;

        // issue global loads for next slab early (latency hidden by FFMAs)
        if (s + 1 < NSLABS) {
            int g0 = ((s + 1) * BK + kk0) * NPTS;
            int g1 = ((s + 1) * BK + kk1) * NPTS;
            pa0 = *(const float4*)&A[g0 + bm0 + mm0];
            pa1 = *(const float4*)&A[g1 + bm0 + mm1];
            pb0 = *(const float4*)&B[g0 + bn0 + mm0];
            pb1 = *(const float4*)&B[g1 + bn0 + mm1];
        }

#pragma unroll
        for (int kk = 0; kk < BK; kk++) {
            float a[8], b[8];
            *(float4*)&a[0] = *(const float4*)&As[kk * BM + ty * 8];
            *(float4*)&a[4] = *(const float4*)&As[kk * BM + ty * 8 + 4];
            *(float4*)&b[0] = *(const float4*)&Bs[kk * BN + tx * 8];
            *(float4*)&b[4] = *(const float4*)&Bs[kk * BN + tx * 8 + 4];
#pragma unroll
            for (int i = 0; i < 8; i++)
#pragma unroll
                for (int j = 0; j < 8; j++)
                    acc[i][j] = fmaf(a[i], b[j], acc[i][j]);
        }

        // stage next slab into the other buffer (readers finished it last iter)
        if (s + 1 < NSLABS) {
            float* Ad = smem + ((s + 1) & 1) * BUF_FLOATS;
            float* Bd = Ad + 2048;
            *(float4*)&Ad[kk0 * BM + mm0] = pa0;
            *(float4*)&Ad[kk1 * BM + mm1] = pa1;
            *(float4*)&Bd[kk0 * BN + mm0] = pb0;
            *(float4*)&Bd[kk1 * BN + mm1] = pb1;
        }
        __syncthreads();
    }

    // epilogue: scale by inverse norms, stage full tile in smem
    float ia[8], ib[8];
#pragma unroll
    for (int i = 0; i < 8; i++) {
        ia[i] = g_invA[bm0 + ty * 8 + i];
        ib[i] = g_invB[bn0 + tx * 8 + i];
    }
#pragma unroll
    for (int i = 0; i < 8; i++)
#pragma unroll
        for (int j = 0; j < 8; j++)
            tile[(ty * 8 + i) * TILE_LD + tx * 8 + j] = acc[i][j] * ia[i] * ib[j];
    __syncthreads();

    // top-2 scans: threads 0..127 rows, 128..255 columns (pad -> conflict-free)
    if (tid < 128) {
        int r = tid;
        float v0 = -2.f, v1 = -2.f;
        int   i0 = 0,    i1 = 0;
#pragma unroll 4
        for (int j = 0; j < BN; j++) {
            float v = tile[r * TILE_LD + j];
            if (v > v0) { v1 = v0; i1 = i0; v0 = v; i0 = bn0 + j; }
            else if (v > v1) { v1 = v; i1 = bn0 + j; }
        }
        int base = ((bm0 + r) * NTILES + bj) * 2;
        g_rowPV[base] = v0; g_rowPV[base + 1] = v1;
        g_rowPI[base] = i0; g_rowPI[base + 1] = i1;
    } else {
        int c = tid - 128;
        float v0 = -2.f, v1 = -2.f;
        int   i0 = 0,    i1 = 0;
#pragma unroll 4
        for (int r = 0; r < BM; r++) {
            float v = tile[r * TILE_LD + c];
            if (v > v0) { v1 = v0; i1 = i0; v0 = v; i0 = bm0 + r; }
            else if (v > v1) { v1 = v; i1 = bm0 + r; }
        }
        int base = ((bn0 + c) * NTILES + bi) * 2;
        g_colPV[base] = v0; g_colPV[base + 1] = v1;
        g_colPI[base] = i0; g_colPI[base + 1] = i1;
    }
}

// ---------------- kernel 3: merge partials -----------------------------------
__global__ void merge_kernel() {
    int t = blockIdx.x * blockDim.x + threadIdx.x;
    if (t < NPTS) {
        int r = t;
        float v0 = -2.f, v1 = -2.f;
        int   i0 = 0,    i1 = 0;
        for (int tt = 0; tt < NTILES; tt++) {
            int base = (r * NTILES + tt) * 2;
            float a0 = g_rowPV[base];     int j0 = g_rowPI[base];
            float a1 = g_rowPV[base + 1]; int j1 = g_rowPI[base + 1];
            if (a0 > v0) { v1 = v0; i1 = i0; v0 = a0; i0 = j0; }
            else if (a0 > v1) { v1 = a0; i1 = j0; }
            if (a1 > v0) { v1 = v0; i1 = i0; v0 = a1; i0 = j1; }
            else if (a1 > v1) { v1 = a1; i1 = j1; }
        }
        g_nn12[r] = i0; g_s12_0[r] = v0; g_s12_1[r] = v1;
    } else if (t < 2 * NPTS) {
        int c = t - NPTS;
        float v0 = -2.f, v1 = -2.f;
        int   i0 = 0,    i1 = 0;
        for (int tt = 0; tt < NTILES; tt++) {
            int base = (c * NTILES + tt) * 2;
            float a0 = g_colPV[base];     int j0 = g_colPI[base];
            float a1 = g_colPV[base + 1]; int j1 = g_colPI[base + 1];
            if (a0 > v0) { v1 = v0; i1 = i0; v0 = a0; i0 = j0; }
            else if (a0 > v1) { v1 = a0; i1 = j0; }
            if (a1 > v0) { v1 = v0; i1 = i0; v0 = a1; i0 = j1; }
            else if (a1 > v1) { v1 = a1; i1 = j1; }
        }
        float d0 = 2.f - 2.f * v0;
        float d1 = 2.f - 2.f * v1;
        g_nn21[c] = i0;
        g_r21[c]  = d0 / (d1 + 1e-8f);
    }
}

// ---------------- kernel 4: mutual NN + ratio mask, write outputs ------------
__global__ void final_kernel(float* __restrict__ out) {
    int r = blockIdx.x * blockDim.x + threadIdx.x;
    if (r >= NPTS) return;
    int   j  = g_nn12[r];
    float s0 = g_s12_0[r];
    float s1 = g_s12_1[r];
    float ratio12 = (2.f - 2.f * s0) / ((2.f - 2.f * s1) + 1e-8f);
    bool m = (g_nn21[j] == r) && (ratio12 <= 0.95f) && (g_r21[j] <= 0.95f);
    out[r]             = m ? s0 : 0.f;      // masked_sim
    out[NPTS + r]      = (float)j;          // nn12
    out[2 * NPTS + r]  = m ? 1.f : 0.f;     // mask
}

// ---------------- launcher ----------------------------------------------------
extern "C" void kernel_launch(void* const* d_in, const int* in_sizes, int n_in,
                              void* d_out, int out_size) {
    const float* A = (const float*)d_in[0];
    const float* B = (const float*)d_in[1];
    float* out = (float*)d_out;

    const int smem_bytes = BM * TILE_LD * sizeof(float);  // 66048 B >= 2*16KB bufs
    cudaFuncSetAttribute(gemm_top2_kernel,
                         cudaFuncAttributeMaxDynamicSharedMemorySize, smem_bytes);

    invnorm_kernel<<<(NPTS + 255) / 256, 256>>>(A, B);

    dim3 grid(NTILES, NTILES);
    gemm_top2_kernel<<<grid, 256, smem_bytes>>>(A, B);

    merge_kernel<<<(2 * NPTS + 255) / 256, 256>>>();

    final_kernel<<<(NPTS + 255) / 256, 256>>>(out);
}

// round 13
// speedup vs baseline: 1.4777x; 1.1902x over previous
#include <cuda_runtime.h>
#include <math.h>
#include <stdint.h>

// ---------------- problem constants ------------------------------------------
#define NPTS 12288
#define KD   512
#define NTILES 96        // 12288/128 tiles in both M and N
#define BM   128
#define BN   128
#define NCH  32          // K chunks of 16
#define NTHREADS 256
#define TILE_LD 129

// smem: 3 pipeline stages of 32KB (8192 floats) each; tile view aliases them
#define STAGE_FLOATS 8192
#define SMEM_BYTES   98304   // 3 * 32768 >= 128*129*4 = 66048

// ---------------- PTX helpers -------------------------------------------------
#define MMA_TF32(c, a, b) \
    asm volatile("mma.sync.aligned.m16n8k8.row.col.f32.tf32.tf32.f32 " \
        "{%0,%1,%2,%3}, {%4,%5,%6,%7}, {%8,%9}, {%0,%1,%2,%3};" \
        : "+f"((c)[0]), "+f"((c)[1]), "+f"((c)[2]), "+f"((c)[3]) \
        : "r"((a)[0]), "r"((a)[1]), "r"((a)[2]), "r"((a)[3]), \
          "r"((b)[0]), "r"((b)[1]))

#define CP_ASYNC16(dst_u32, src_ptr) \
    asm volatile("cp.async.ca.shared.global [%0], [%1], 16;" \
        :: "r"(dst_u32), "l"(src_ptr) : "memory")
#define CP_COMMIT() asm volatile("cp.async.commit_group;" ::: "memory")
#define CP_WAIT1()  asm volatile("cp.async.wait_group 1;" ::: "memory")

__device__ __forceinline__ uint32_t smem_to_u32(const void* p) {
    uint32_t a;
    asm("{ .reg .u64 t; cvta.to.shared.u64 t, %1; cvt.u32.u64 %0, t; }" : "=r"(a) : "l"(p));
    return a;
}
__device__ __forceinline__ void tf32_split(float v, float& h, float& l) {
    uint32_t hb, lb;
    asm("cvt.rna.tf32.f32 %0, %1;" : "=r"(hb) : "f"(v));
    h = __uint_as_float(hb);
    float r = v - h;
    asm("cvt.rna.tf32.f32 %0, %1;" : "=r"(lb) : "f"(r));
    l = __uint_as_float(lb);
}

// ---------------- scratch (device globals: allocation-guard safe) ------------
// A packed in m16n8k8 A-fragment order: [m_tile(768)][k_tile(64)][lane(32)][4]
__device__ float g_Ah[NPTS * KD];
__device__ float g_Al[NPTS * KD];
// B packed in B-fragment order: [n_tile(1536)][k_tile(64)][lane(32)][2]
__device__ float g_Bh[NPTS * KD];
__device__ float g_Bl[NPTS * KD];
__device__ float g_invA[NPTS];
__device__ float g_invB[NPTS];
__device__ float g_rowPV[NPTS * NTILES * 2];
__device__ int   g_rowPI[NPTS * NTILES * 2];
__device__ float g_colPV[NPTS * NTILES * 2];
__device__ int   g_colPI[NPTS * NTILES * 2];
__device__ int   g_nn12[NPTS];
__device__ float g_s12_0[NPTS];
__device__ float g_s12_1[NPTS];
__device__ int   g_nn21[NPTS];
__device__ float g_r21[NPTS];

// ---------------- kernel 0a: pack A (hi/lo tf32, fragment order) --------------
// src layout [KD][NPTS]; A-frag element map for (m16,k8) tile:
// e0=(g,t) e1=(g+8,t) e2=(g,t+4) e3=(g+8,t+4), g=lane>>2, t=lane&3
__global__ void convertA_kernel(const float* __restrict__ A) {
    int lane = threadIdx.x;
    int kt = blockIdx.y * blockDim.y + threadIdx.y;   // 0..63
    int mt = blockIdx.x;                               // 0..767
    int g = lane >> 2, t = lane & 3;
    int m0 = mt * 16, k0 = kt * 8;
    float v0 = A[(k0 + t)     * NPTS + m0 + g];
    float v1 = A[(k0 + t)     * NPTS + m0 + g + 8];
    float v2 = A[(k0 + t + 4) * NPTS + m0 + g];
    float v3 = A[(k0 + t + 4) * NPTS + m0 + g + 8];
    float4 h, l;
    tf32_split(v0, h.x, l.x); tf32_split(v1, h.y, l.y);
    tf32_split(v2, h.z, l.z); tf32_split(v3, h.w, l.w);
    size_t base = ((size_t)(mt * 64 + kt) * 32 + lane) * 4;
    *(float4*)&g_Ah[base] = h;
    *(float4*)&g_Al[base] = l;
}

// ---------------- kernel 0b: pack B (hi/lo tf32, fragment order) --------------
// B-frag map for (n8,k8) tile: b0=(k=t, n=g), b1=(k=t+4, n=g)
__global__ void convertB_kernel(const float* __restrict__ B) {
    int lane = threadIdx.x;
    int kt = blockIdx.y * blockDim.y + threadIdx.y;   // 0..63
    int nt = blockIdx.x;                               // 0..1535
    int g = lane >> 2, t = lane & 3;
    int n0 = nt * 8, k0 = kt * 8;
    float v0 = B[(k0 + t)     * NPTS + n0 + g];
    float v1 = B[(k0 + t + 4) * NPTS + n0 + g];
    float2 h, l;
    tf32_split(v0, h.x, l.x); tf32_split(v1, h.y, l.y);
    size_t base = ((size_t)(nt * 64 + kt) * 32 + lane) * 2;
    *(float2*)&g_Bh[base] = h;
    *(float2*)&g_Bl[base] = l;
}

// ---------------- kernel 1: inverse L2 norms ----------------------------------
__global__ void invnorm_kernel(const float* __restrict__ A, const float* __restrict__ B) {
    int p = blockIdx.x * blockDim.x + threadIdx.x;
    if (p >= NPTS) return;
    float sa = 0.f, sb = 0.f;
#pragma unroll 8
    for (int c = 0; c < KD; c++) {
        float a = A[c * NPTS + p];
        float b = B[c * NPTS + p];
        sa = fmaf(a, a, sa);
        sb = fmaf(b, b, sb);
    }
    g_invA[p] = 1.0f / sqrtf(sa);
    g_invB[p] = 1.0f / sqrtf(sb);
}

// ---------------- kernel 2: mma.sync 3xTF32 GEMM + per-tile top-2 -------------
// Stage layout (floats, per 8192-float stage):
//   Ah [0,2048): kt2*1024 + mt*128 + lane*4 + e      (8 m-tiles, 2 k-tiles)
//   Al [2048,4096), Bh [4096,6144): kt2*1024 + nt*64 + lane*2 + e  (16 n-tiles)
//   Bl [6144,8192)
__device__ __forceinline__ void stage_chunk(uint32_t smem_u32,
                                            int s, int ch, int bi, int bj, int tid) {
    uint32_t sb = smem_u32 + s * STAGE_FLOATS * 4;
#pragma unroll
    for (int h = 0; h < 2; h++) {
        const float* gA = h ? g_Al : g_Ah;
        const float* gB = h ? g_Bl : g_Bh;
        uint32_t sA = sb + h * 2048 * 4;
        uint32_t sB = sb + (4096 + h * 2048) * 4;
#pragma unroll
        for (int v = 0; v < 2; v++) {
            int f = tid + v * 256;                    // 0..511 float4 slots
            int kt2 = f >> 8;
            int mt  = (f >> 5) & 7, qa = f & 31;
            const float* srcA = gA + ((size_t)((bi * 8 + mt) * 64 + ch * 2 + kt2)) * 128 + qa * 4;
            CP_ASYNC16(sA + (kt2 * 1024 + mt * 128 + qa * 4) * 4, srcA);
            int nt  = (f >> 4) & 15, qb = f & 15;
            const float* srcB = gB + ((size_t)((bj * 16 + nt) * 64 + ch * 2 + kt2)) * 64 + qb * 4;
            CP_ASYNC16(sB + (kt2 * 1024 + nt * 64 + qb * 4) * 4, srcB);
        }
    }
    CP_COMMIT();
}

__global__ void __launch_bounds__(NTHREADS, 1)
gemm_mma_kernel() {
    extern __shared__ float smem[];
    const uint32_t smem_u32 = smem_to_u32(smem);
    const int tid  = threadIdx.x;
    const int wid  = tid >> 5;
    const int lane = tid & 31;
    const int wm   = wid >> 2;          // 0..1 -> 64-row half
    const int wn   = wid & 3;           // 0..3 -> 32-col quarter
    const int bj = blockIdx.x;
    const int bi = blockIdx.y;
    const int bm0 = bi * BM;
    const int bn0 = bj * BN;

    float acc[4][4][4];
#pragma unroll
    for (int i = 0; i < 4; i++)
#pragma unroll
        for (int j = 0; j < 4; j++)
#pragma unroll
            for (int e = 0; e < 4; e++) acc[i][j][e] = 0.f;

    // prologue: stages for chunks 0 and 1 in flight
    stage_chunk(smem_u32, 0, 0, bi, bj, tid);
    stage_chunk(smem_u32, 1, 1, bi, bj, tid);

    for (int ch = 0; ch < NCH; ch++) {
        CP_WAIT1();                     // chunk ch landed (ch+1 may be in flight)
        __syncthreads();
        const int s = ch % 3;
        const float* base = smem + s * STAGE_FLOATS;

#pragma unroll
        for (int kt2 = 0; kt2 < 2; kt2++) {
            const float* Ah_s = base + kt2 * 1024;
            const float* Al_s = base + 2048 + kt2 * 1024;
            const float* Bh_s = base + 4096 + kt2 * 1024;
            const float* Bl_s = base + 6144 + kt2 * 1024;

            uint32_t ah[4][4], bh[4][2];
#pragma unroll
            for (int i = 0; i < 4; i++)
                *(uint4*)ah[i] = *(const uint4*)(Ah_s + (wm * 4 + i) * 128 + lane * 4);
#pragma unroll
            for (int j = 0; j < 4; j++)
                *(uint2*)bh[j] = *(const uint2*)(Bh_s + (wn * 4 + j) * 64 + lane * 2);
#pragma unroll
            for (int i = 0; i < 4; i++)
#pragma unroll
                for (int j = 0; j < 4; j++)
                    MMA_TF32(acc[i][j], ah[i], bh[j]);

            uint32_t bl[4][2];
#pragma unroll
            for (int j = 0; j < 4; j++)
                *(uint2*)bl[j] = *(const uint2*)(Bl_s + (wn * 4 + j) * 64 + lane * 2);
#pragma unroll
            for (int i = 0; i < 4; i++)
#pragma unroll
                for (int j = 0; j < 4; j++)
                    MMA_TF32(acc[i][j], ah[i], bl[j]);

            uint32_t al[4][4];
#pragma unroll
            for (int i = 0; i < 4; i++)
                *(uint4*)al[i] = *(const uint4*)(Al_s + (wm * 4 + i) * 128 + lane * 4);
#pragma unroll
            for (int i = 0; i < 4; i++)
#pragma unroll
                for (int j = 0; j < 4; j++)
                    MMA_TF32(acc[i][j], al[i], bh[j]);
        }

        if (ch + 2 < NCH)
            stage_chunk(smem_u32, (ch + 2) % 3, ch + 2, bi, bj, tid);
    }
    __syncthreads();

    // epilogue: scale by inverse norms, stage full 128x128 tile in smem
    float* tile = smem;
    {
        int g = lane >> 2, t = lane & 3;
#pragma unroll
        for (int i = 0; i < 4; i++) {
            int r0 = wm * 64 + i * 16 + g;
            int r1 = r0 + 8;
            float ia0 = g_invA[bm0 + r0];
            float ia1 = g_invA[bm0 + r1];
#pragma unroll
            for (int j = 0; j < 4; j++) {
                int c0 = wn * 32 + j * 8 + t * 2;
                float ib0 = g_invB[bn0 + c0];
                float ib1 = g_invB[bn0 + c0 + 1];
                tile[r0 * TILE_LD + c0]     = acc[i][j][0] * ia0 * ib0;
                tile[r0 * TILE_LD + c0 + 1] = acc[i][j][1] * ia0 * ib1;
                tile[r1 * TILE_LD + c0]     = acc[i][j][2] * ia1 * ib0;
                tile[r1 * TILE_LD + c0 + 1] = acc[i][j][3] * ia1 * ib1;
            }
        }
    }
    __syncthreads();

    // top-2 scans: threads 0..127 rows, 128..255 columns (pad -> conflict-free)
    if (tid < 128) {
        int r = tid;
        float v0 = -2.f, v1 = -2.f;
        int   i0 = 0,    i1 = 0;
#pragma unroll 4
        for (int j = 0; j < BN; j++) {
            float v = tile[r * TILE_LD + j];
            if (v > v0) { v1 = v0; i1 = i0; v0 = v; i0 = bn0 + j; }
            else if (v > v1) { v1 = v; i1 = bn0 + j; }
        }
        int base = ((bm0 + r) * NTILES + bj) * 2;
        g_rowPV[base] = v0; g_rowPV[base + 1] = v1;
        g_rowPI[base] = i0; g_rowPI[base + 1] = i1;
    } else {
        int c = tid - 128;
        float v0 = -2.f, v1 = -2.f;
        int   i0 = 0,    i1 = 0;
#pragma unroll 4
        for (int r = 0; r < BM; r++) {
            float v = tile[r * TILE_LD + c];
            if (v > v0) { v1 = v0; i1 = i0; v0 = v; i0 = bm0 + r; }
            else if (v > v1) { v1 = v; i1 = bm0 + r; }
        }
        int base = ((bn0 + c) * NTILES + bi) * 2;
        g_colPV[base] = v0; g_colPV[base + 1] = v1;
        g_colPI[base] = i0; g_colPI[base + 1] = i1;
    }
}

// ---------------- kernel 3: merge partials ------------------------------------
__global__ void merge_kernel() {
    int t = blockIdx.x * blockDim.x + threadIdx.x;
    if (t < NPTS) {
        int r = t;
        float v0 = -2.f, v1 = -2.f;
        int   i0 = 0,    i1 = 0;
        for (int tt = 0; tt < NTILES; tt++) {
            int base = (r * NTILES + tt) * 2;
            float a0 = g_rowPV[base];     int j0 = g_rowPI[base];
            float a1 = g_rowPV[base + 1]; int j1 = g_rowPI[base + 1];
            if (a0 > v0) { v1 = v0; i1 = i0; v0 = a0; i0 = j0; }
            else if (a0 > v1) { v1 = a0; i1 = j0; }
            if (a1 > v0) { v1 = v0; i1 = i0; v0 = a1; i0 = j1; }
            else if (a1 > v1) { v1 = a1; i1 = j1; }
        }
        g_nn12[r] = i0; g_s12_0[r] = v0; g_s12_1[r] = v1;
    } else if (t < 2 * NPTS) {
        int c = t - NPTS;
        float v0 = -2.f, v1 = -2.f;
        int   i0 = 0,    i1 = 0;
        for (int tt = 0; tt < NTILES; tt++) {
            int base = (c * NTILES + tt) * 2;
            float a0 = g_colPV[base];     int j0 = g_colPI[base];
            float a1 = g_colPV[base + 1]; int j1 = g_colPI[base + 1];
            if (a0 > v0) { v1 = v0; i1 = i0; v0 = a0; i0 = j0; }
            else if (a0 > v1) { v1 = a0; i1 = j0; }
            if (a1 > v0) { v1 = v0; i1 = i0; v0 = a1; i0 = j1; }
            else if (a1 > v1) { v1 = a1; i1 = j1; }
        }
        float d0 = 2.f - 2.f * v0;
        float d1 = 2.f - 2.f * v1;
        g_nn21[c] = i0;
        g_r21[c]  = d0 / (d1 + 1e-8f);
    }
}

// ---------------- kernel 4: mutual NN + ratio mask, write outputs -------------
__global__ void final_kernel(float* __restrict__ out) {
    int r = blockIdx.x * blockDim.x + threadIdx.x;
    if (r >= NPTS) return;
    int   j  = g_nn12[r];
    float s0 = g_s12_0[r];
    float s1 = g_s12_1[r];
    float ratio12 = (2.f - 2.f * s0) / ((2.f - 2.f * s1) + 1e-8f);
    bool m = (g_nn21[j] == r) && (ratio12 <= 0.95f) && (g_r21[j] <= 0.95f);
    out[r]            = m ? s0 : 0.f;   // masked_sim
    out[NPTS + r]     = (float)j;       // nn12
    out[2 * NPTS + r] = m ? 1.f : 0.f;  // mask
}

// ---------------- launcher -----------------------------------------------------
extern "C" void kernel_launch(void* const* d_in, const int* in_sizes, int n_in,
                              void* d_out, int out_size) {
    const float* A = (const float*)d_in[0];
    const float* B = (const float*)d_in[1];
    float* out = (float*)d_out;

    cudaFuncSetAttribute(gemm_mma_kernel,
                         cudaFuncAttributeMaxDynamicSharedMemorySize, SMEM_BYTES);

    convertA_kernel<<<dim3(NPTS / 16, 8), dim3(32, 8)>>>(A);
    convertB_kernel<<<dim3(NPTS / 8, 8), dim3(32, 8)>>>(B);
    invnorm_kernel<<<(NPTS + 255) / 256, 256>>>(A, B);
    gemm_mma_kernel<<<dim3(NTILES, NTILES), NTHREADS, SMEM_BYTES>>>();
    merge_kernel<<<(2 * NPTS + 255) / 256, 256>>>();
    final_kernel<<<(NPTS + 255) / 256, 256>>>(out);
}

// round 15
// speedup vs baseline: 1.7834x; 1.2069x over previous
#include <cuda_runtime.h>
#include <math.h>
#include <stdint.h>

// ---------------- problem constants ------------------------------------------
#define NPTS 12288
#define KD   512
#define NTILES 96        // 12288/128 tiles in both M and N
#define BM   128
#define BN   128
#define NCH  32          // K chunks of 16
#define NTHREADS 256
#define TILE_LD 129

// smem: 4 pipeline stages of 16KB (4096 floats); tile view (66048B) aliases them
#define STAGE_FLOATS 4096
#define NSTAGE 4
#define SMEM_BYTES 66048   // 128*129*4 >= 4*16384

// ---------------- PTX helpers -------------------------------------------------
#define MMA_TF32(c, a, b) \
    asm volatile("mma.sync.aligned.m16n8k8.row.col.f32.tf32.tf32.f32 " \
        "{%0,%1,%2,%3}, {%4,%5,%6,%7}, {%8,%9}, {%0,%1,%2,%3};" \
        : "+f"((c)[0]), "+f"((c)[1]), "+f"((c)[2]), "+f"((c)[3]) \
        : "r"((a)[0]), "r"((a)[1]), "r"((a)[2]), "r"((a)[3]), \
          "r"((b)[0]), "r"((b)[1]))

#define CP_ASYNC16(dst_u32, src_ptr) \
    asm volatile("cp.async.ca.shared.global [%0], [%1], 16;" \
        :: "r"(dst_u32), "l"(src_ptr) : "memory")
#define CP_COMMIT() asm volatile("cp.async.commit_group;" ::: "memory")
#define CP_WAIT2()  asm volatile("cp.async.wait_group 2;" ::: "memory")

__device__ __forceinline__ uint32_t smem_to_u32(const void* p) {
    uint32_t a;
    asm("{ .reg .u64 t; cvta.to.shared.u64 t, %1; cvt.u32.u64 %0, t; }" : "=r"(a) : "l"(p));
    return a;
}
// split fp32 -> tf32-exact hi (19 top bits) + residual lo (HW truncates lo's tail)
__device__ __forceinline__ void split1(uint32_t a, uint32_t& h, uint32_t& l) {
    h = a & 0xFFFFE000u;
    l = __float_as_uint(__uint_as_float(a) - __uint_as_float(h));
}

// ---------------- scratch (device globals: allocation-guard safe) ------------
// A packed in m16n8k8 A-fragment order: [m_tile(768)][k_tile(64)][lane(32)][4]
__device__ float g_Ap[NPTS * KD];
// B packed in B-fragment order: [n_tile(1536)][k_tile(64)][lane(32)][2]
__device__ float g_Bp[NPTS * KD];
__device__ float g_invA[NPTS];
__device__ float g_invB[NPTS];
__device__ float g_rowPV[NPTS * NTILES * 2];
__device__ int   g_rowPI[NPTS * NTILES * 2];
__device__ float g_colPV[NPTS * NTILES * 2];
__device__ int   g_colPI[NPTS * NTILES * 2];
__device__ int   g_nn12[NPTS];
__device__ float g_s12_0[NPTS];
__device__ float g_s12_1[NPTS];
__device__ int   g_nn21[NPTS];
__device__ float g_r21[NPTS];

// ---------------- kernel 0a: pack A (fp32, fragment order) --------------------
// src layout [KD][NPTS]; A-frag element map for (m16,k8) tile:
// e0=(g,t) e1=(g+8,t) e2=(g,t+4) e3=(g+8,t+4), g=lane>>2, t=lane&3
__global__ void convertA_kernel(const float* __restrict__ A) {
    int lane = threadIdx.x;
    int kt = blockIdx.y * blockDim.y + threadIdx.y;   // 0..63
    int mt = blockIdx.x;                               // 0..767
    int g = lane >> 2, t = lane & 3;
    int m0 = mt * 16, k0 = kt * 8;
    float4 v;
    v.x = A[(k0 + t)     * NPTS + m0 + g];
    v.y = A[(k0 + t)     * NPTS + m0 + g + 8];
    v.z = A[(k0 + t + 4) * NPTS + m0 + g];
    v.w = A[(k0 + t + 4) * NPTS + m0 + g + 8];
    size_t base = ((size_t)(mt * 64 + kt) * 32 + lane) * 4;
    *(float4*)&g_Ap[base] = v;
}

// ---------------- kernel 0b: pack B (fp32, fragment order) --------------------
// B-frag map for (n8,k8) tile: b0=(k=t, n=g), b1=(k=t+4, n=g)
__global__ void convertB_kernel(const float* __restrict__ B) {
    int lane = threadIdx.x;
    int kt = blockIdx.y * blockDim.y + threadIdx.y;   // 0..63
    int nt = blockIdx.x;                               // 0..1535
    int g = lane >> 2, t = lane & 3;
    int n0 = nt * 8, k0 = kt * 8;
    float2 v;
    v.x = B[(k0 + t)     * NPTS + n0 + g];
    v.y = B[(k0 + t + 4) * NPTS + n0 + g];
    size_t base = ((size_t)(nt * 64 + kt) * 32 + lane) * 2;
    *(float2*)&g_Bp[base] = v;
}

// ---------------- kernel 1: inverse L2 norms ----------------------------------
__global__ void invnorm_kernel(const float* __restrict__ A, const float* __restrict__ B) {
    int p = blockIdx.x * blockDim.x + threadIdx.x;
    if (p >= NPTS) return;
    float sa = 0.f, sb = 0.f;
#pragma unroll 8
    for (int c = 0; c < KD; c++) {
        float a = A[c * NPTS + p];
        float b = B[c * NPTS + p];
        sa = fmaf(a, a, sa);
        sb = fmaf(b, b, sb);
    }
    g_invA[p] = 1.0f / sqrtf(sa);
    g_invB[p] = 1.0f / sqrtf(sb);
}

// ---------------- kernel 2: mma.sync 3xTF32 GEMM + per-tile top-2 -------------
// Stage layout (floats, per 4096-float stage):
//   A [0,2048):    kt2*1024 + mt*128 + lane*4 + e   (8 m-tiles, 2 k-tiles)
//   B [2048,4096): 2048 + kt2*1024 + nt*64 + lane*2 + e  (16 n-tiles)
__device__ __forceinline__ void stage_chunk(uint32_t smem_u32,
                                            int s, int ch, int bi, int bj, int tid) {
    uint32_t sb = smem_u32 + s * STAGE_FLOATS * 4;
#pragma unroll
    for (int v = 0; v < 2; v++) {
        int f = tid + v * 256;                    // 0..511 float4 slots
        int kt2 = f >> 8;
        int mt  = (f >> 5) & 7, qa = f & 31;
        const float* srcA = g_Ap + ((size_t)((bi * 8 + mt) * 64 + ch * 2 + kt2)) * 128 + qa * 4;
        CP_ASYNC16(sb + (kt2 * 1024 + mt * 128 + qa * 4) * 4, srcA);
        int nt  = (f >> 4) & 15, qb = f & 15;
        const float* srcB = g_Bp + ((size_t)((bj * 16 + nt) * 64 + ch * 2 + kt2)) * 64 + qb * 4;
        CP_ASYNC16(sb + (2048 + kt2 * 1024 + nt * 64 + qb * 4) * 4, srcB);
    }
    CP_COMMIT();
}

__global__ void __launch_bounds__(NTHREADS, 1)
gemm_mma_kernel() {
    extern __shared__ float smem[];
    const uint32_t smem_u32 = smem_to_u32(smem);
    const int tid  = threadIdx.x;
    const int wid  = tid >> 5;
    const int lane = tid & 31;
    const int wm   = wid >> 2;          // 0..1 -> 64-row half
    const int wn   = wid & 3;           // 0..3 -> 32-col quarter
    const int bj = blockIdx.x;
    const int bi = blockIdx.y;
    const int bm0 = bi * BM;
    const int bn0 = bj * BN;

    float acc[4][4][4];
#pragma unroll
    for (int i = 0; i < 4; i++)
#pragma unroll
        for (int j = 0; j < 4; j++)
#pragma unroll
            for (int e = 0; e < 4; e++) acc[i][j][e] = 0.f;

    // prologue: chunks 0..2 in flight
    stage_chunk(smem_u32, 0, 0, bi, bj, tid);
    stage_chunk(smem_u32, 1, 1, bi, bj, tid);
    stage_chunk(smem_u32, 2, 2, bi, bj, tid);

    for (int ch = 0; ch < NCH; ch++) {
        CP_WAIT2();                     // chunk ch landed (ch+1, ch+2 may be in flight)
        __syncthreads();
        const float* base = smem + (ch & (NSTAGE - 1)) * STAGE_FLOATS;

#pragma unroll
        for (int kt2 = 0; kt2 < 2; kt2++) {
            const float* As = base + kt2 * 1024;
            const float* Bs = base + 2048 + kt2 * 1024;

            uint32_t ar[4][4], br[4][2];
#pragma unroll
            for (int i = 0; i < 4; i++)
                *(uint4*)ar[i] = *(const uint4*)(As + (wm * 4 + i) * 128 + lane * 4);
#pragma unroll
            for (int j = 0; j < 4; j++)
                *(uint2*)br[j] = *(const uint2*)(Bs + (wn * 4 + j) * 64 + lane * 2);

            // in-register tf32 hi/lo split
            uint32_t ah[4][4], al[4][4], bh[4][2], bl[4][2];
#pragma unroll
            for (int i = 0; i < 4; i++)
#pragma unroll
                for (int e = 0; e < 4; e++) split1(ar[i][e], ah[i][e], al[i][e]);
#pragma unroll
            for (int j = 0; j < 4; j++)
#pragma unroll
                for (int e = 0; e < 2; e++) split1(br[j][e], bh[j][e], bl[j][e]);

#pragma unroll
            for (int i = 0; i < 4; i++)
#pragma unroll
                for (int j = 0; j < 4; j++)
                    MMA_TF32(acc[i][j], ah[i], bh[j]);
#pragma unroll
            for (int i = 0; i < 4; i++)
#pragma unroll
                for (int j = 0; j < 4; j++)
                    MMA_TF32(acc[i][j], ah[i], bl[j]);
#pragma unroll
            for (int i = 0; i < 4; i++)
#pragma unroll
                for (int j = 0; j < 4; j++)
                    MMA_TF32(acc[i][j], al[i], bh[j]);
        }

        if (ch + 3 < NCH)
            stage_chunk(smem_u32, (ch + 3) & (NSTAGE - 1), ch + 3, bi, bj, tid);
    }
    __syncthreads();

    // epilogue: scale by inverse norms, stage full 128x128 tile in smem
    float* tile = smem;
    {
        int g = lane >> 2, t = lane & 3;
#pragma unroll
        for (int i = 0; i < 4; i++) {
            int r0 = wm * 64 + i * 16 + g;
            int r1 = r0 + 8;
            float ia0 = g_invA[bm0 + r0];
            float ia1 = g_invA[bm0 + r1];
#pragma unroll
            for (int j = 0; j < 4; j++) {
                int c0 = wn * 32 + j * 8 + t * 2;
                float ib0 = g_invB[bn0 + c0];
                float ib1 = g_invB[bn0 + c0 + 1];
                tile[r0 * TILE_LD + c0]     = acc[i][j][0] * ia0 * ib0;
                tile[r0 * TILE_LD + c0 + 1] = acc[i][j][1] * ia0 * ib1;
                tile[r1 * TILE_LD + c0]     = acc[i][j][2] * ia1 * ib0;
                tile[r1 * TILE_LD + c0 + 1] = acc[i][j][3] * ia1 * ib1;
            }
        }
    }
    __syncthreads();

    // top-2 scans: threads 0..127 rows, 128..255 columns (pad -> conflict-free)
    if (tid < 128) {
        int r = tid;
        float v0 = -2.f, v1 = -2.f;
        int   i0 = 0,    i1 = 0;
#pragma unroll 4
        for (int j = 0; j < BN; j++) {
            float v = tile[r * TILE_LD + j];
            if (v > v0) { v1 = v0; i1 = i0; v0 = v; i0 = bn0 + j; }
            else if (v > v1) { v1 = v; i1 = bn0 + j; }
        }
        int base = ((bm0 + r) * NTILES + bj) * 2;
        g_rowPV[base] = v0; g_rowPV[base + 1] = v1;
        g_rowPI[base] = i0; g_rowPI[base + 1] = i1;
    } else {
        int c = tid - 128;
        float v0 = -2.f, v1 = -2.f;
        int   i0 = 0,    i1 = 0;
#pragma unroll 4
        for (int r = 0; r < BM; r++) {
            float v = tile[r * TILE_LD + c];
            if (v > v0) { v1 = v0; i1 = i0; v0 = v; i0 = bm0 + r; }
            else if (v > v1) { v1 = v; i1 = bm0 + r; }
        }
        int base = ((bn0 + c) * NTILES + bi) * 2;
        g_colPV[base] = v0; g_colPV[base + 1] = v1;
        g_colPI[base] = i0; g_colPI[base + 1] = i1;
    }
}

// ---------------- kernel 3: merge partials ------------------------------------
__global__ void merge_kernel() {
    int t = blockIdx.x * blockDim.x + threadIdx.x;
    if (t < NPTS) {
        int r = t;
        float v0 = -2.f, v1 = -2.f;
        int   i0 = 0,    i1 = 0;
        for (int tt = 0; tt < NTILES; tt++) {
            int base = (r * NTILES + tt) * 2;
            float a0 = g_rowPV[base];     int j0 = g_rowPI[base];
            float a1 = g_rowPV[base + 1]; int j1 = g_rowPI[base + 1];
            if (a0 > v0) { v1 = v0; i1 = i0; v0 = a0; i0 = j0; }
            else if (a0 > v1) { v1 = a0; i1 = j0; }
            if (a1 > v0) { v1 = v0; i1 = i0; v0 = a1; i0 = j1; }
            else if (a1 > v1) { v1 = a1; i1 = j1; }
        }
        g_nn12[r] = i0; g_s12_0[r] = v0; g_s12_1[r] = v1;
    } else if (t < 2 * NPTS) {
        int c = t - NPTS;
        float v0 = -2.f, v1 = -2.f;
        int   i0 = 0,    i1 = 0;
        for (int tt = 0; tt < NTILES; tt++) {
            int base = (c * NTILES + tt) * 2;
            float a0 = g_colPV[base];     int j0 = g_colPI[base];
            float a1 = g_colPV[base + 1]; int j1 = g_colPI[base + 1];
            if (a0 > v0) { v1 = v0; i1 = i0; v0 = a0; i0 = j0; }
            else if (a0 > v1) { v1 = a0; i1 = j0; }
            if (a1 > v0) { v1 = v0; i1 = i0; v0 = a1; i0 = j1; }
            else if (a1 > v1) { v1 = a1; i1 = j1; }
        }
        float d0 = 2.f - 2.f * v0;
        float d1 = 2.f - 2.f * v1;
        g_nn21[c] = i0;
        g_r21[c]  = d0 / (d1 + 1e-8f);
    }
}

// ---------------- kernel 4: mutual NN + ratio mask, write outputs -------------
__global__ void final_kernel(float* __restrict__ out) {
    int r = blockIdx.x * blockDim.x + threadIdx.x;
    if (r >= NPTS) return;
    int   j  = g_nn12[r];
    float s0 = g_s12_0[r];
    float s1 = g_s12_1[r];
    float ratio12 = (2.f - 2.f * s0) / ((2.f - 2.f * s1) + 1e-8f);
    bool m = (g_nn21[j] == r) && (ratio12 <= 0.95f) && (g_r21[j] <= 0.95f);
    out[r]            = m ? s0 : 0.f;   // masked_sim
    out[NPTS + r]     = (float)j;       // nn12
    out[2 * NPTS + r] = m ? 1.f : 0.f;  // mask
}

// ---------------- launcher -----------------------------------------------------
extern "C" void kernel_launch(void* const* d_in, const int* in_sizes, int n_in,
                              void* d_out, int out_size) {
    const float* A = (const float*)d_in[0];
    const float* B = (const float*)d_in[1];
    float* out = (float*)d_out;

    cudaFuncSetAttribute(gemm_mma_kernel,
                         cudaFuncAttributeMaxDynamicSharedMemorySize, SMEM_BYTES);

    convertA_kernel<<<dim3(NPTS / 16, 8), dim3(32, 8)>>>(A);
    convertB_kernel<<<dim3(NPTS / 8, 8), dim3(32, 8)>>>(B);
    invnorm_kernel<<<(NPTS + 255) / 256, 256>>>(A, B);
    gemm_mma_kernel<<<dim3(NTILES, NTILES), NTHREADS, SMEM_BYTES>>>();
    merge_kernel<<<(2 * NPTS + 255) / 256, 256>>>();
    final_kernel<<<(NPTS + 255) / 256, 256>>>(out);
}

// round 17
// speedup vs baseline: 1.8180x; 1.0194x over previous
#include <cuda_runtime.h>
#include <math.h>
#include <stdint.h>

// ---------------- problem constants ------------------------------------------
#define NPTS 12288
#define KD   512
#define NTILES 96        // 12288/128 tiles in both M and N
#define BM   128
#define BN   128
#define NCH  16          // K chunks of 32
#define NTHREADS 256
#define TILE_LD 129

// smem: 3 pipeline stages of 32KB (8192 floats); tile view (66048B) aliases them
#define STAGE_FLOATS 8192
#define NSTAGE 3
#define SMEM_BYTES 98304   // 3*32768 >= 128*129*4

// ---------------- PTX helpers -------------------------------------------------
#define MMA_TF32(c, a, b) \
    asm volatile("mma.sync.aligned.m16n8k8.row.col.f32.tf32.tf32.f32 " \
        "{%0,%1,%2,%3}, {%4,%5,%6,%7}, {%8,%9}, {%0,%1,%2,%3};" \
        : "+f"((c)[0]), "+f"((c)[1]), "+f"((c)[2]), "+f"((c)[3]) \
        : "r"((a)[0]), "r"((a)[1]), "r"((a)[2]), "r"((a)[3]), \
          "r"((b)[0]), "r"((b)[1]))

#define CP_ASYNC16(dst_u32, src_ptr) \
    asm volatile("cp.async.ca.shared.global [%0], [%1], 16;" \
        :: "r"(dst_u32), "l"(src_ptr) : "memory")
#define CP_COMMIT() asm volatile("cp.async.commit_group;" ::: "memory")
#define CP_WAIT1()  asm volatile("cp.async.wait_group 1;" ::: "memory")

__device__ __forceinline__ uint32_t smem_to_u32(const void* p) {
    uint32_t a;
    asm("{ .reg .u64 t; cvta.to.shared.u64 t, %1; cvt.u32.u64 %0, t; }" : "=r"(a) : "l"(p));
    return a;
}
// residual lo = a - tf32_hi(a); hi itself is never materialized (MMA truncates
// raw fp32 operands to tf32 in HW, so raw a serves as the hi operand).
__device__ __forceinline__ uint32_t tf32_lo(uint32_t a) {
    uint32_t nah = (a & 0xFFFFE000u) ^ 0x80000000u;   // one LOP3: -hi(a)
    return __float_as_uint(__uint_as_float(a) + __uint_as_float(nah));
}

// ---------------- scratch (device globals: allocation-guard safe) ------------
// A packed in m16n8k8 A-fragment order: [m_tile(768)][k_tile(64)][lane(32)][4]
__device__ float g_Ap[NPTS * KD];
// B packed in B-fragment order: [n_tile(1536)][k_tile(64)][lane(32)][2]
__device__ float g_Bp[NPTS * KD];
__device__ float g_invA[NPTS];
__device__ float g_invB[NPTS];
__device__ float g_rowPV[NPTS * NTILES * 2];
__device__ int   g_rowPI[NPTS * NTILES * 2];
__device__ float g_colPV[NPTS * NTILES * 2];
__device__ int   g_colPI[NPTS * NTILES * 2];
__device__ int   g_nn12[NPTS];
__device__ float g_s12_0[NPTS];
__device__ float g_s12_1[NPTS];
__device__ int   g_nn21[NPTS];
__device__ float g_r21[NPTS];

// ---------------- kernel 0a: pack A (fp32, fragment order) --------------------
// src layout [KD][NPTS]; A-frag element map for (m16,k8) tile:
// e0=(g,t) e1=(g+8,t) e2=(g,t+4) e3=(g+8,t+4), g=lane>>2, t=lane&3
__global__ void convertA_kernel(const float* __restrict__ A) {
    int lane = threadIdx.x;
    int kt = blockIdx.y * blockDim.y + threadIdx.y;   // 0..63
    int mt = blockIdx.x;                               // 0..767
    int g = lane >> 2, t = lane & 3;
    int m0 = mt * 16, k0 = kt * 8;
    float4 v;
    v.x = A[(k0 + t)     * NPTS + m0 + g];
    v.y = A[(k0 + t)     * NPTS + m0 + g + 8];
    v.z = A[(k0 + t + 4) * NPTS + m0 + g];
    v.w = A[(k0 + t + 4) * NPTS + m0 + g + 8];
    size_t base = ((size_t)(mt * 64 + kt) * 32 + lane) * 4;
    *(float4*)&g_Ap[base] = v;
}

// ---------------- kernel 0b: pack B (fp32, fragment order) --------------------
// B-frag map for (n8,k8) tile: b0=(k=t, n=g), b1=(k=t+4, n=g)
__global__ void convertB_kernel(const float* __restrict__ B) {
    int lane = threadIdx.x;
    int kt = blockIdx.y * blockDim.y + threadIdx.y;   // 0..63
    int nt = blockIdx.x;                               // 0..1535
    int g = lane >> 2, t = lane & 3;
    int n0 = nt * 8, k0 = kt * 8;
    float2 v;
    v.x = B[(k0 + t)     * NPTS + n0 + g];
    v.y = B[(k0 + t + 4) * NPTS + n0 + g];
    size_t base = ((size_t)(nt * 64 + kt) * 32 + lane) * 2;
    *(float2*)&g_Bp[base] = v;
}

// ---------------- kernel 1: inverse L2 norms ----------------------------------
__global__ void invnorm_kernel(const float* __restrict__ A, const float* __restrict__ B) {
    int p = blockIdx.x * blockDim.x + threadIdx.x;
    if (p >= NPTS) return;
    float sa = 0.f, sb = 0.f;
#pragma unroll 8
    for (int c = 0; c < KD; c++) {
        float a = A[c * NPTS + p];
        float b = B[c * NPTS + p];
        sa = fmaf(a, a, sa);
        sb = fmaf(b, b, sb);
    }
    g_invA[p] = 1.0f / sqrtf(sa);
    g_invB[p] = 1.0f / sqrtf(sb);
}

// ---------------- kernel 2: mma.sync 3xTF32 GEMM + per-tile top-2 -------------
// Stage layout (floats, per 8192-float stage), K-chunk = 32 (4 k-tiles):
//   A [0,4096):    kt2*1024 + mt*128 + lane*4 + e   (8 m-tiles, 4 k-tiles)
//   B [4096,8192): 4096 + kt2*1024 + nt*64 + lane*2 + e  (16 n-tiles)
__device__ __forceinline__ void stage_chunk(uint32_t smem_u32,
                                            int s, int ch, int bi, int bj, int tid) {
    uint32_t sb = smem_u32 + s * STAGE_FLOATS * 4;
#pragma unroll
    for (int v = 0; v < 4; v++) {
        int f = tid + v * 256;                    // 0..1023 float4 slots
        int kt2 = f >> 8;                         // 0..3
        int mt  = (f >> 5) & 7, qa = f & 31;
        const float* srcA = g_Ap + ((size_t)((bi * 8 + mt) * 64 + ch * 4 + kt2)) * 128 + qa * 4;
        CP_ASYNC16(sb + (kt2 * 1024 + mt * 128 + qa * 4) * 4, srcA);
        int nt  = (f >> 4) & 15, qb = f & 15;
        const float* srcB = g_Bp + ((size_t)((bj * 16 + nt) * 64 + ch * 4 + kt2)) * 64 + qb * 4;
        CP_ASYNC16(sb + (4096 + kt2 * 1024 + nt * 64 + qb * 4) * 4, srcB);
    }
    CP_COMMIT();
}

__global__ void __launch_bounds__(NTHREADS, 2)
gemm_mma_kernel() {
    extern __shared__ float smem[];
    const uint32_t smem_u32 = smem_to_u32(smem);
    const int tid  = threadIdx.x;
    const int wid  = tid >> 5;
    const int lane = tid & 31;
    const int wm   = wid >> 2;          // 0..1 -> 64-row half
    const int wn   = wid & 3;           // 0..3 -> 32-col quarter
    const int bj = blockIdx.x;
    const int bi = blockIdx.y;
    const int bm0 = bi * BM;
    const int bn0 = bj * BN;

    float acc[4][4][4];
#pragma unroll
    for (int i = 0; i < 4; i++)
#pragma unroll
        for (int j = 0; j < 4; j++)
#pragma unroll
            for (int e = 0; e < 4; e++) acc[i][j][e] = 0.f;

    // prologue: chunks 0 and 1 in flight
    stage_chunk(smem_u32, 0, 0, bi, bj, tid);
    stage_chunk(smem_u32, 1, 1, bi, bj, tid);

    for (int ch = 0; ch < NCH; ch++) {
        CP_WAIT1();                     // chunk ch landed (ch+1 may be in flight)
        __syncthreads();
        // issue next chunk's loads BEFORE compute so DMA overlaps the MMAs
        if (ch + 2 < NCH)
            stage_chunk(smem_u32, (ch + 2) % NSTAGE, ch + 2, bi, bj, tid);

        const float* base = smem + (ch % NSTAGE) * STAGE_FLOATS;

#pragma unroll
        for (int kt2 = 0; kt2 < 4; kt2++) {
            const float* As = base + kt2 * 1024;
            const float* Bs = base + 4096 + kt2 * 1024;

            uint32_t ar[4][4], br[4][2];
#pragma unroll
            for (int i = 0; i < 4; i++)
                *(uint4*)ar[i] = *(const uint4*)(As + (wm * 4 + i) * 128 + lane * 4);
#pragma unroll
            for (int j = 0; j < 4; j++)
                *(uint2*)br[j] = *(const uint2*)(Bs + (wn * 4 + j) * 64 + lane * 2);

            // pass 1: raw x raw (HW truncates both to tf32 hi)
#pragma unroll
            for (int i = 0; i < 4; i++)
#pragma unroll
                for (int j = 0; j < 4; j++)
                    MMA_TF32(acc[i][j], ar[i], br[j]);

            // pass 2: raw(a) x lo(b) = ah*bl
            uint32_t bl[4][2];
#pragma unroll
            for (int j = 0; j < 4; j++)
#pragma unroll
                for (int e = 0; e < 2; e++) bl[j][e] = tf32_lo(br[j][e]);
#pragma unroll
            for (int i = 0; i < 4; i++)
#pragma unroll
                for (int j = 0; j < 4; j++)
                    MMA_TF32(acc[i][j], ar[i], bl[j]);

            // pass 3: lo(a) x raw(b) = al*bh
            uint32_t al[4][4];
#pragma unroll
            for (int i = 0; i < 4; i++)
#pragma unroll
                for (int e = 0; e < 4; e++) al[i][e] = tf32_lo(ar[i][e]);
#pragma unroll
            for (int i = 0; i < 4; i++)
#pragma unroll
                for (int j = 0; j < 4; j++)
                    MMA_TF32(acc[i][j], al[i], br[j]);
        }
    }
    __syncthreads();

    // epilogue: scale by inverse norms, stage full 128x128 tile in smem
    float* tile = smem;
    {
        int g = lane >> 2, t = lane & 3;
#pragma unroll
        for (int i = 0; i < 4; i++) {
            int r0 = wm * 64 + i * 16 + g;
            int r1 = r0 + 8;
            float ia0 = g_invA[bm0 + r0];
            float ia1 = g_invA[bm0 + r1];
#pragma unroll
            for (int j = 0; j < 4; j++) {
                int c0 = wn * 32 + j * 8 + t * 2;
                float ib0 = g_invB[bn0 + c0];
                float ib1 = g_invB[bn0 + c0 + 1];
                tile[r0 * TILE_LD + c0]     = acc[i][j][0] * ia0 * ib0;
                tile[r0 * TILE_LD + c0 + 1] = acc[i][j][1] * ia0 * ib1;
                tile[r1 * TILE_LD + c0]     = acc[i][j][2] * ia1 * ib0;
                tile[r1 * TILE_LD + c0 + 1] = acc[i][j][3] * ia1 * ib1;
            }
        }
    }
    __syncthreads();

    // top-2 scans: threads 0..127 rows, 128..255 columns (pad -> conflict-free)
    if (tid < 128) {
        int r = tid;
        float v0 = -2.f, v1 = -2.f;
        int   i0 = 0,    i1 = 0;
#pragma unroll 4
        for (int j = 0; j < BN; j++) {
            float v = tile[r * TILE_LD + j];
            if (v > v0) { v1 = v0; i1 = i0; v0 = v; i0 = bn0 + j; }
            else if (v > v1) { v1 = v; i1 = bn0 + j; }
        }
        int base = ((bm0 + r) * NTILES + bj) * 2;
        g_rowPV[base] = v0; g_rowPV[base + 1] = v1;
        g_rowPI[base] = i0; g_rowPI[base + 1] = i1;
    } else {
        int c = tid - 128;
        float v0 = -2.f, v1 = -2.f;
        int   i0 = 0,    i1 = 0;
#pragma unroll 4
        for (int r = 0; r < BM; r++) {
            float v = tile[r * TILE_LD + c];
            if (v > v0) { v1 = v0; i1 = i0; v0 = v; i0 = bm0 + r; }
            else if (v > v1) { v1 = v; i1 = bm0 + r; }
        }
        int base = ((bn0 + c) * NTILES + bi) * 2;
        g_colPV[base] = v0; g_colPV[base + 1] = v1;
        g_colPI[base] = i0; g_colPI[base + 1] = i1;
    }
}

// ---------------- kernel 3: merge partials ------------------------------------
__global__ void merge_kernel() {
    int t = blockIdx.x * blockDim.x + threadIdx.x;
    if (t < NPTS) {
        int r = t;
        float v0 = -2.f, v1 = -2.f;
        int   i0 = 0,    i1 = 0;
        for (int tt = 0; tt < NTILES; tt++) {
            int base = (r * NTILES + tt) * 2;
            float a0 = g_rowPV[base];     int j0 = g_rowPI[base];
            float a1 = g_rowPV[base + 1]; int j1 = g_rowPI[base + 1];
            if (a0 > v0) { v1 = v0; i1 = i0; v0 = a0; i0 = j0; }
            else if (a0 > v1) { v1 = a0; i1 = j0; }
            if (a1 > v0) { v1 = v0; i1 = i0; v0 = a1; i0 = j1; }
            else if (a1 > v1) { v1 = a1; i1 = j1; }
        }
        g_nn12[r] = i0; g_s12_0[r] = v0; g_s12_1[r] = v1;
    } else if (t < 2 * NPTS) {
        int c = t - NPTS;
        float v0 = -2.f, v1 = -2.f;
        int   i0 = 0,    i1 = 0;
        for (int tt = 0; tt < NTILES; tt++) {
            int base = (c * NTILES + tt) * 2;
            float a0 = g_colPV[base];     int j0 = g_colPI[base];
            float a1 = g_colPV[base + 1]; int j1 = g_colPI[base + 1];
            if (a0 > v0) { v1 = v0; i1 = i0; v0 = a0; i0 = j0; }
            else if (a0 > v1) { v1 = a0; i1 = j0; }
            if (a1 > v0) { v1 = v0; i1 = i0; v0 = a1; i0 = j1; }
            else if (a1 > v1) { v1 = a1; i1 = j1; }
        }
        float d0 = 2.f - 2.f * v0;
        float d1 = 2.f - 2.f * v1;
        g_nn21[c] = i0;
        g_r21[c]  = d0 / (d1 + 1e-8f);
    }
}

// ---------------- kernel 4: mutual NN + ratio mask, write outputs -------------
__global__ void final_kernel(float* __restrict__ out) {
    int r = blockIdx.x * blockDim.x + threadIdx.x;
    if (r >= NPTS) return;
    int   j  = g_nn12[r];
    float s0 = g_s12_0[r];
    float s1 = g_s12_1[r];
    float ratio12 = (2.f - 2.f * s0) / ((2.f - 2.f * s1) + 1e-8f);
    bool m = (g_nn21[j] == r) && (ratio12 <= 0.95f) && (g_r21[j] <= 0.95f);
    out[r]            = m ? s0 : 0.f;   // masked_sim
    out[NPTS + r]     = (float)j;       // nn12
    out[2 * NPTS + r] = m ? 1.f : 0.f;  // mask
}

// ---------------- launcher -----------------------------------------------------
extern "C" void kernel_launch(void* const* d_in, const int* in_sizes, int n_in,
                              void* d_out, int out_size) {
    const float* A = (const float*)d_in[0];
    const float* B = (const float*)d_in[1];
    float* out = (float*)d_out;

    cudaFuncSetAttribute(gemm_mma_kernel,
                         cudaFuncAttributeMaxDynamicSharedMemorySize, SMEM_BYTES);

    convertA_kernel<<<dim3(NPTS / 16, 8), dim3(32, 8)>>>(A);
    convertB_kernel<<<dim3(NPTS / 8, 8), dim3(32, 8)>>>(B);
    invnorm_kernel<<<(NPTS + 255) / 256, 256>>>(A, B);
    gemm_mma_kernel<<<dim3(NTILES, NTILES), NTHREADS, SMEM_BYTES>>>();
    merge_kernel<<<(2 * NPTS + 255) / 256, 256>>>();
    final_kernel<<<(NPTS + 255) / 256, 256>>>(out);
}